// round 5
// baseline (speedup 1.0000x reference)
#include <cuda_runtime.h>

#define NQ      10000
#define D       128
#define NHEADS  8
#define NPOINTS 4
#define HSP     51
#define WSP     102
#define HW      (HSP * WSP)
#define NL      50
#define HD      16
#define TPB     256
#define GRID    592

// Scratch (device globals; no allocation allowed).
// 128B alignment makes even-x pair blocks exactly one 128B line.
__device__ __align__(128) float g_proj[NHEADS * HW * HD];  // [h][spatial][16ch]
__device__ unsigned g_arrive = 0;
__device__ unsigned g_depart = 0;

// ---------------------------------------------------------------------------
__global__ void __launch_bounds__(TPB, 4)
fused_kernel(const float* __restrict__ query,
             const float* __restrict__ value,
             const float* __restrict__ ref,
             const float* __restrict__ W_off,
             const float* __restrict__ b_off,
             const float* __restrict__ W_attn,
             const float* __restrict__ b_attn,
             const float* __restrict__ W_val,
             const float* __restrict__ b_val,
             const float* __restrict__ W_out,
             const float* __restrict__ b_out,
             const float* __restrict__ W_proj,
             float* __restrict__ out,
             float* __restrict__ out_idx,
             int n_idx,
             float* __restrict__ tailp,
             int tail_n) {
    __shared__ float s_msda[NL * D];      // 25.6 KB
    __shared__ float s_q[D];
    __shared__ float s_avg[D];
    __shared__ float s_off[64];           // pre-normalized offsets (x,y per h,p)
    __shared__ float s_aw[32];            // point softmax weights
    __shared__ float s_wp[D];             // W_out @ W_proj
    __shared__ float s_wts[64];           // level logits -> weights
    __shared__ float s_refy[NL];
    __shared__ float s_refx;
    __shared__ float s_part[D];
    __shared__ float s_wx[64];            // slow path: masked x-corner weights
    __shared__ int   s_cx[64];            // slow path: clamped x-corner coords
    __shared__ int   s_x0raw[32];         // raw x0 per (h,p)
    __shared__ float s_wx0m[32], s_wx1m[32];
    __shared__ float s_wx4[NHEADS * NPOINTS * 4]; // aw-folded 4-col weights
    __shared__ int   s_xb[NHEADS];        // even window base per head
    __shared__ int   s_wide[NHEADS];      // fallback flag per head
    __shared__ float s_lg[NL * 9];        // per-(l,h) logit partials, pad 9
    __shared__ float s_val[2 * D];        // phase-0 staging

    const float* __restrict__ proj = g_proj;
    int tid = threadIdx.x;

    // ===================== phase 0: value projection ========================
    {
        int ch = tid & 127;
        int half = tid >> 7;
        for (int s0 = blockIdx.x * 2; s0 < HW; s0 += GRID * 2) {
            int s = s0 + half;
            bool ok = s < HW;
            __syncthreads();
            if (ok) s_val[half * D + ch] = value[s * D + ch];
            __syncthreads();
            if (ok) {
                float acc = b_val[ch];
                const float* vr = &s_val[half * D];
#pragma unroll 8
                for (int k = 0; k < D; k++)
                    acc = fmaf(vr[k], W_val[k * D + ch], acc);
                g_proj[(ch >> 4) * (HW * HD) + s * HD + (ch & 15)] = acc;
            }
        }
        for (int i = blockIdx.x * TPB + tid; i < tail_n; i += GRID * TPB)
            tailp[i] = 0.f;
    }

    // ===================== device-wide barrier ==============================
    __syncthreads();
    if (tid == 0) {
        __threadfence();
        atomicAdd(&g_arrive, 1u);
        while (*(volatile unsigned*)&g_arrive < GRID) { }
        __threadfence();
        unsigned old = atomicAdd(&g_depart, 1u);
        if (old == GRID - 1) {
            *(volatile unsigned*)&g_arrive = 0u;
            __threadfence();
            *(volatile unsigned*)&g_depart = 0u;
        }
    }
    __syncthreads();

    // ===================== wp = W_out @ W_proj ==============================
    {
        if (tid < D) s_avg[tid] = W_proj[tid];
        __syncthreads();
        int warp = tid >> 5, lane = tid & 31;
        for (int r = warp; r < D; r += 8) {
            float a = 0.f;
#pragma unroll
            for (int kk = 0; kk < 4; kk++) {
                int k = lane + kk * 32;
                a = fmaf(W_out[r * D + k], s_avg[k], a);
            }
#pragma unroll
            for (int o = 16; o; o >>= 1)
                a += __shfl_down_sync(0xffffffffu, a, o);
            if (lane == 0) s_wp[r] = a;
        }
    }

    // ===================== phase 1: per-query attention =====================
    for (int q = blockIdx.x; q < NQ; q += GRID) {
        __syncthreads();
        if (tid < D) s_q[tid] = query[q * D + tid];
        __syncthreads();

        // ---- offsets (64) + attn logits (32): 192-thread k-split GEMV;
        //      warps 6-7 load ref y per level (+ the z-invariant x)
        if (tid < 192) {
            int col = tid >> 1;
            int half = tid & 1;
            bool is_off = col < 64;
            const float* W = is_off ? (W_off + col) : (W_attn + (col - 64));
            int stride = is_off ? 64 : 32;
            float acc = 0.f;
            if (half == 0)
                acc = is_off ? b_off[col] : b_attn[col - 64];
            int k0 = half * 64;
#pragma unroll 8
            for (int k = 0; k < 64; k++)
                acc = fmaf(s_q[k0 + k], W[(k0 + k) * stride], acc);
            acc += __shfl_xor_sync(0xffffffffu, acc, 1);
            if (half == 0) {
                if (is_off)
                    s_off[col] = acc / ((col & 1) ? (float)HSP : (float)WSP);
                else
                    s_aw[col - 64] = acc;
            }
        } else {
            int i = tid - 192;
            if (i < NL)
                s_refy[i] = ref[i * (NQ * 2) + q * 2 + 1];
            else if (i == NL)
                s_refx = ref[q * 2 + 0];
        }
        __syncthreads();

        // ---- step1: point softmax (tid<8) + per-(h,p) x precompute (32..63)
        if (tid < NHEADS) {
            float m = s_aw[tid * 4];
#pragma unroll
            for (int p = 1; p < 4; p++) m = fmaxf(m, s_aw[tid * 4 + p]);
            float e[4]; float ssum = 0.f;
#pragma unroll
            for (int p = 0; p < 4; p++) {
                e[p] = expf(s_aw[tid * 4 + p] - m);
                ssum += e[p];
            }
            float inv = 1.f / ssum;
#pragma unroll
            for (int p = 0; p < 4; p++) s_aw[tid * 4 + p] = e[p] * inv;
        } else if (tid >= 32 && tid < 64) {
            int up = tid - 32;
            float px = (s_refx + s_off[up * 2]) * (float)WSP - 0.5f;
            float x0f = floorf(px);
            float dx = px - x0f;
            int x0 = (int)x0f;
            float w0 = ((unsigned)x0 < WSP) ? (1.f - dx) : 0.f;
            float w1 = ((unsigned)(x0 + 1) < WSP) ? dx : 0.f;
            s_x0raw[up] = x0;
            s_wx0m[up] = w0;
            s_wx1m[up] = w1;
            s_wx[up * 2 + 0] = w0;
            s_wx[up * 2 + 1] = w1;
            s_cx[up * 2 + 0] = min(max(x0, 0), WSP - 1);
            s_cx[up * 2 + 1] = min(max(x0 + 1, 0), WSP - 1);
        }
        __syncthreads();

        // ---- step2: per-head even x-window + aw-folded 4-col weights
        if (tid < NHEADS) {
            int h = tid;
            int xlo = s_x0raw[h * 4];
#pragma unroll
            for (int p = 1; p < 4; p++) xlo = min(xlo, s_x0raw[h * 4 + p]);
            int xb = min(max(xlo & ~1, 0), WSP - 4);
            int wide = 0;
#pragma unroll
            for (int p = 0; p < 4; p++) {
                int up = h * 4 + p;
                float aw = s_aw[up];
                int c0 = s_x0raw[up] - xb;
                int c1 = c0 + 1;
                float w0 = s_wx0m[up], w1 = s_wx1m[up];
                if (w0 != 0.f && (c0 < 0 || c0 > 3)) wide = 1;
                if (w1 != 0.f && (c1 < 0 || c1 > 3)) wide = 1;
                float wc[4] = {0.f, 0.f, 0.f, 0.f};
                if (c0 >= 0 && c0 <= 3) wc[c0] += w0;
                if (c1 >= 0 && c1 <= 3) wc[c1] += w1;
#pragma unroll
                for (int c = 0; c < 4; c++)
                    s_wx4[up * 4 + c] = wc[c] * aw;
            }
            s_xb[h] = xb;
            s_wide[h] = wide;
        }
        __syncthreads();

        // ---- MSDA sampling: unit = (level, head), 8 lanes per unit.
        {
            int j = tid & 7;
            int slot = tid >> 3;
            int cA = j >> 2;                 // 0/1 -> cols {xb,xb+1} vs {xb+2,xb+3}
            int cidx = (j & 3) * 4;
            for (int u = slot; u < NL * NHEADS; u += 32) {
                int l = u >> 3, h = u & 7;
                float ry = s_refy[l];
                float a0 = 0.f, a1 = 0.f, a2 = 0.f, a3 = 0.f;
                if (!s_wide[h]) {
                    // fast path: distinct-row loop over even-aligned 4-col window
                    int y0a[4]; float dya[4];
                    int ylo = 0x3fffffff, yhi = -0x3fffffff;
#pragma unroll
                    for (int p = 0; p < 4; p++) {
                        float py = (ry + s_off[(h * 4 + p) * 2 + 1]) * (float)HSP - 0.5f;
                        float y0f = floorf(py);
                        int y0 = (int)y0f;
                        y0a[p] = y0;
                        dya[p] = py - y0f;
                        ylo = min(ylo, y0);
                        yhi = max(yhi, y0 + 1);
                    }
                    ylo = max(ylo, 0);
                    yhi = min(yhi, HSP - 1);
                    float wxA[4], wxB[4];
#pragma unroll
                    for (int p = 0; p < 4; p++) {
                        wxA[p] = s_wx4[(h * 4 + p) * 4 + cA];
                        wxB[p] = s_wx4[(h * 4 + p) * 4 + cA + 2];
                    }
                    const float* bA = proj + h * (HW * HD) + s_xb[h] * HD + j * 4;
                    for (int y = ylo; y <= yhi; y++) {
                        float wA = 0.f, wB = 0.f;
#pragma unroll
                        for (int p = 0; p < 4; p++) {
                            float t = (y == y0a[p]) ? (1.f - dya[p])
                                     : ((y == y0a[p] + 1) ? dya[p] : 0.f);
                            wA = fmaf(t, wxA[p], wA);
                            wB = fmaf(t, wxB[p], wB);
                        }
                        const float* rp = bA + y * (WSP * HD);
                        float4 vA = *(const float4*)rp;
                        float4 vB = *(const float4*)(rp + 32);
                        a0 = fmaf(wA, vA.x, fmaf(wB, vB.x, a0));
                        a1 = fmaf(wA, vA.y, fmaf(wB, vB.y, a1));
                        a2 = fmaf(wA, vA.z, fmaf(wB, vB.z, a2));
                        a3 = fmaf(wA, vA.w, fmaf(wB, vB.w, a3));
                    }
                } else {
                    // slow path: exact original per-point gather
                    const float* basep = proj + h * (HW * HD) + cidx;
#pragma unroll
                    for (int p = 0; p < NPOINTS; p++) {
                        int up = h * 4 + p;
                        float py = (ry + s_off[up * 2 + 1]) * (float)HSP - 0.5f;
                        float y0f = floorf(py);
                        float dy = py - y0f;
                        int y0 = (int)y0f;
                        float wy0 = ((unsigned)y0 < HSP) ? (1.f - dy) : 0.f;
                        float wy1 = ((unsigned)(y0 + 1) < HSP) ? dy : 0.f;
                        int cy0 = min(max(y0, 0), HSP - 1);
                        int cy1 = min(max(y0 + 1, 0), HSP - 1);
                        float waw = s_wx[up * 2 + cA] * s_aw[up];
                        int xc = s_cx[up * 2 + cA];
                        const float4* p0 = (const float4*)(basep + (cy0 * WSP + xc) * HD);
                        const float4* p1 = (const float4*)(basep + (cy1 * WSP + xc) * HD);
                        float4 v0 = *p0;
                        float4 v1 = *p1;
                        float w0 = waw * wy0, w1 = waw * wy1;
                        a0 = fmaf(w0, v0.x, fmaf(w1, v1.x, a0));
                        a1 = fmaf(w0, v0.y, fmaf(w1, v1.y, a1));
                        a2 = fmaf(w0, v0.z, fmaf(w1, v1.z, a2));
                        a3 = fmaf(w0, v0.w, fmaf(w1, v1.w, a3));
                    }
                }
                // combine the two column-halves (lanes j and j^4)
                a0 += __shfl_xor_sync(0xffffffffu, a0, 4);
                a1 += __shfl_xor_sync(0xffffffffu, a1, 4);
                a2 += __shfl_xor_sync(0xffffffffu, a2, 4);
                a3 += __shfl_xor_sync(0xffffffffu, a3, 4);
                if (j < 4) {
                    float4 r; r.x = a0; r.y = a1; r.z = a2; r.w = a3;
                    *(float4*)&s_msda[l * D + h * HD + cidx] = r;
                }
                // fused level-logit partial: dot(msda[l,h,:16], wp[h*16:...])
                float dot = a0 * s_wp[h * HD + cidx + 0]
                          + a1 * s_wp[h * HD + cidx + 1]
                          + a2 * s_wp[h * HD + cidx + 2]
                          + a3 * s_wp[h * HD + cidx + 3];
                dot += __shfl_xor_sync(0xffffffffu, dot, 1);
                dot += __shfl_xor_sync(0xffffffffu, dot, 2);
                if (j == 0) s_lg[l * 9 + h] = dot;
            }
        }
        __syncthreads();

        // ---- level softmax + argmax (warp 0; reduces 8 head-partials inline)
        if (tid < 32) {
            float v0 = -3.4e38f, v1 = -3.4e38f;
            if (tid < NL) {
                v0 = 0.f;
#pragma unroll
                for (int h = 0; h < NHEADS; h++) v0 += s_lg[tid * 9 + h];
            }
            if (tid + 32 < NL) {
                v1 = 0.f;
#pragma unroll
                for (int h = 0; h < NHEADS; h++) v1 += s_lg[(tid + 32) * 9 + h];
            }
            float bv; int bi;
            if (v1 > v0) { bv = v1; bi = tid + 32; }
            else         { bv = v0; bi = tid; }
#pragma unroll
            for (int o = 16; o; o >>= 1) {
                float ov = __shfl_down_sync(0xffffffffu, bv, o);
                int   oi = __shfl_down_sync(0xffffffffu, bi, o);
                if (ov > bv || (ov == bv && oi < bi)) { bv = ov; bi = oi; }
            }
            bv = __shfl_sync(0xffffffffu, bv, 0);
            float e0 = (tid < NL) ? expf(v0 - bv) : 0.f;
            float e1 = (tid + 32 < NL) ? expf(v1 - bv) : 0.f;
            float ssum = e0 + e1;
#pragma unroll
            for (int o = 16; o; o >>= 1)
                ssum += __shfl_xor_sync(0xffffffffu, ssum, o);
            float inv = 1.f / ssum;
            if (tid < NL) s_wts[tid] = e0 * inv;
            if (tid + 32 < NL) s_wts[tid + 32] = e1 * inv;
            if (tid == 0 && q < n_idx) out_idx[q] = (float)bi;
        }
        __syncthreads();

        // ---- weighted average over levels
        if (tid < D) {
            float acc = 0.f;
#pragma unroll 5
            for (int l = 0; l < NL; l++)
                acc = fmaf(s_wts[l], s_msda[l * D + tid], acc);
            s_avg[tid] = acc;
        }
        __syncthreads();

        // ---- final: out = avg @ W_out + b_out + 2*query  (k-split, 256 thr)
        {
            int ch = tid & 127, half = tid >> 7;
            int k0 = half * 64;
            float acc = 0.f;
#pragma unroll 8
            for (int k = 0; k < 64; k++)
                acc = fmaf(s_avg[k0 + k], W_out[(k0 + k) * D + ch], acc);
            if (half) s_part[ch] = acc;
            __syncthreads();
            if (!half)
                out[q * D + ch] = acc + s_part[ch] + b_out[ch] + 2.0f * s_q[ch];
        }
    }
}

// ---------------------------------------------------------------------------
extern "C" void kernel_launch(void* const* d_in, const int* in_sizes, int n_in,
                              void* d_out, int out_size) {
    const float* query  = (const float*)d_in[0];
    const float* value  = (const float*)d_in[1];
    const float* refp   = (const float*)d_in[2];
    const float* W_off  = (const float*)d_in[3];
    const float* b_off  = (const float*)d_in[4];
    const float* W_attn = (const float*)d_in[5];
    const float* b_attn = (const float*)d_in[6];
    const float* W_val  = (const float*)d_in[7];
    const float* b_val  = (const float*)d_in[8];
    const float* W_out  = (const float*)d_in[9];
    const float* b_out  = (const float*)d_in[10];
    const float* W_proj = (const float*)d_in[11];
    // b_proj (d_in[12]) unused: constant shift is softmax/argmax-invariant.

    float* out = (float*)d_out;

    int n_idx = out_size - NQ * D;
    if (n_idx < 0) n_idx = 0;
    if (n_idx > NQ) n_idx = NQ;

    int tail_n = out_size - (NQ * D + NQ);
    float* tailp = out + NQ * D + NQ;
    if (tail_n < 0) { tail_n = 0; tailp = out; }

    fused_kernel<<<GRID, TPB>>>(query, value, refp, W_off, b_off,
                                W_attn, b_attn, W_val, b_val,
                                W_out, b_out, W_proj,
                                out, out + NQ * D, n_idx, tailp, tail_n);
}

// round 7
// speedup vs baseline: 1.0459x; 1.0459x over previous
#include <cuda_runtime.h>
#include <cuda_fp16.h>

#define NQ      10000
#define D       128
#define NHEADS  8
#define NPOINTS 4
#define HSP     51
#define WSP     102
#define HW      (HSP * WSP)
#define NL      50
#define HD      16
#define TPB     256
#define GRID    592

// Scratch (device globals; no allocation allowed).
__device__ __align__(128) __half g_projh[NHEADS * HW * HD];  // fp16 table 1.33MB
__device__ float g_G[NHEADS * HW];    // fp32 scalar field: dot(proj_row, wp_h)
__device__ unsigned g_arrive = 0;
__device__ unsigned g_depart = 0;

// ---------------------------------------------------------------------------
__global__ void __launch_bounds__(TPB, 4)
fused_kernel(const float* __restrict__ query,
             const float* __restrict__ value,
             const float* __restrict__ ref,
             const float* __restrict__ W_off,
             const float* __restrict__ b_off,
             const float* __restrict__ W_attn,
             const float* __restrict__ b_attn,
             const float* __restrict__ W_val,
             const float* __restrict__ b_val,
             const float* __restrict__ W_out,
             const float* __restrict__ b_out,
             const float* __restrict__ W_proj,
             float* __restrict__ out,
             float* __restrict__ out_idx,
             int n_idx,
             float* __restrict__ tailp,
             int tail_n) {
    __shared__ float s_msda[NL * D];      // 25.6 KB
    __shared__ float s_q[D];
    __shared__ float s_avg[D];
    __shared__ float s_off[64];           // pre-normalized offsets (x,y per h,p)
    __shared__ float s_aw[32];            // point softmax weights
    __shared__ float s_wp[D];             // W_out @ W_proj
    __shared__ float s_wts[64];           // level weights
    __shared__ float s_refy[NL];
    __shared__ float s_refx;
    __shared__ float s_part[D];
    __shared__ float s_wx[64];            // masked x-corner weights per (h,p)
    __shared__ int   s_cx[64];            // clamped x-corner coords per (h,p)
    __shared__ float s_lg[NL * 9];        // per-(l,h) logit partials, pad 9
    __shared__ float s_val[2 * D];        // phase-0 staging

    const __half* __restrict__ proj = g_projh;
    int tid = threadIdx.x;

    // ===================== wp = W_out @ W_proj (needed in phase 0) ==========
    {
        if (tid < D) s_avg[tid] = W_proj[tid];
        __syncthreads();
        int warp = tid >> 5, lane = tid & 31;
        for (int r = warp; r < D; r += 8) {
            float a = 0.f;
#pragma unroll
            for (int kk = 0; kk < 4; kk++) {
                int k = lane + kk * 32;
                a = fmaf(W_out[r * D + k], s_avg[k], a);
            }
#pragma unroll
            for (int o = 16; o; o >>= 1)
                a += __shfl_down_sync(0xffffffffu, a, o);
            if (lane == 0) s_wp[r] = a;
        }
        __syncthreads();
    }

    // ===================== phase 0: value projection (fp32->fp16 + G) =======
    {
        int ch = tid & 127;
        int half_ = tid >> 7;
        float wpc = s_wp[ch];
        for (int s0 = blockIdx.x * 2; s0 < HW; s0 += GRID * 2) {
            int s = s0 + half_;
            bool ok = s < HW;
            __syncthreads();
            if (ok) s_val[half_ * D + ch] = value[s * D + ch];
            __syncthreads();
            float acc = 0.f;
            if (ok) {
                acc = b_val[ch];
                const float* vr = &s_val[half_ * D];
#pragma unroll 8
                for (int k = 0; k < D; k++)
                    acc = fmaf(vr[k], W_val[k * D + ch], acc);
                g_projh[(ch >> 4) * (HW * HD) + s * HD + (ch & 15)] =
                    __float2half(acc);
            }
            // fp32 scalar field G[h][s] = sum_c proj_fp32 * wp (16-lane reduce)
            float gterm = acc * wpc;
#pragma unroll
            for (int o = 1; o < 16; o <<= 1)
                gterm += __shfl_xor_sync(0xffffffffu, gterm, o);
            if (ok && (tid & 15) == 0)
                g_G[(ch >> 4) * HW + s] = gterm;
        }
        for (int i = blockIdx.x * TPB + tid; i < tail_n; i += GRID * TPB)
            tailp[i] = 0.f;
    }

    // ===================== device-wide barrier ==============================
    __syncthreads();
    if (tid == 0) {
        __threadfence();
        atomicAdd(&g_arrive, 1u);
        while (*(volatile unsigned*)&g_arrive < GRID) { }
        __threadfence();
        unsigned old = atomicAdd(&g_depart, 1u);
        if (old == GRID - 1) {
            *(volatile unsigned*)&g_arrive = 0u;
            __threadfence();
            *(volatile unsigned*)&g_depart = 0u;
        }
    }
    __syncthreads();

    // ===================== phase 1: per-query attention =====================
    for (int q = blockIdx.x; q < NQ; q += GRID) {
        __syncthreads();
        if (tid < D) s_q[tid] = query[q * D + tid];
        __syncthreads();

        // ---- offsets (64) + attn logits (32): 192-thread k-split GEMV;
        //      warps 6-7 load ref y per level (+ the z-invariant x)
        if (tid < 192) {
            int col = tid >> 1;
            int half_ = tid & 1;
            bool is_off = col < 64;
            const float* W = is_off ? (W_off + col) : (W_attn + (col - 64));
            int stride = is_off ? 64 : 32;
            float acc = 0.f;
            if (half_ == 0)
                acc = is_off ? b_off[col] : b_attn[col - 64];
            int k0 = half_ * 64;
#pragma unroll 8
            for (int k = 0; k < 64; k++)
                acc = fmaf(s_q[k0 + k], W[(k0 + k) * stride], acc);
            acc += __shfl_xor_sync(0xffffffffu, acc, 1);
            if (half_ == 0) {
                if (is_off)
                    s_off[col] = acc / ((col & 1) ? (float)HSP : (float)WSP);
                else
                    s_aw[col - 64] = acc;
            }
        } else {
            int i = tid - 192;
            if (i < NL)
                s_refy[i] = ref[i * (NQ * 2) + q * 2 + 1];
            else if (i == NL)
                s_refx = ref[q * 2 + 0];
        }
        __syncthreads();

        // ---- point softmax (tid<8) + per-(h,p) x precompute (tid 32..63)
        if (tid < NHEADS) {
            float m = s_aw[tid * 4];
#pragma unroll
            for (int p = 1; p < 4; p++) m = fmaxf(m, s_aw[tid * 4 + p]);
            float e[4]; float ssum = 0.f;
#pragma unroll
            for (int p = 0; p < 4; p++) {
                e[p] = expf(s_aw[tid * 4 + p] - m);
                ssum += e[p];
            }
            float inv = 1.f / ssum;
#pragma unroll
            for (int p = 0; p < 4; p++) s_aw[tid * 4 + p] = e[p] * inv;
        } else if (tid >= 32 && tid < 64) {
            int up = tid - 32;
            float px = (s_refx + s_off[up * 2]) * (float)WSP - 0.5f;
            float x0f = floorf(px);
            float dx = px - x0f;
            int x0 = (int)x0f;
            s_wx[up * 2 + 0] = ((unsigned)x0 < WSP) ? (1.f - dx) : 0.f;
            s_wx[up * 2 + 1] = ((unsigned)(x0 + 1) < WSP) ? dx : 0.f;
            s_cx[up * 2 + 0] = min(max(x0, 0), WSP - 1);
            s_cx[up * 2 + 1] = min(max(x0 + 1, 0), WSP - 1);
        }
        __syncthreads();

        // ---- MSDA sampling: unit = (level, head), 4 lanes per unit.
        //      lane bits: bit1 = x-corner, bit0 = channel octet (8 ch).
        //      Lane j also samples the fp32 scalar field G for point p==j
        //      (exact fp32 logit path; fp16 only feeds the bev output).
        {
            int j = tid & 3;
            int slot = tid >> 2;             // 0..63
            int xc = j >> 1;
            int co = (j & 1) * 8;            // channel octet offset (halves)
            for (int u = slot; u < NL * NHEADS; u += 64) {
                int l = u >> 3, h = u & 7;
                float ry = s_refy[l];
                const __half* basep = proj + h * (HW * HD) + co;
                const float* Gh = g_G + h * HW;
                __half2 ac0 = __float2half2_rn(0.f);
                __half2 ac1 = ac0, ac2 = ac0, ac3 = ac0;
                float gdot = 0.f;
#pragma unroll
                for (int p = 0; p < NPOINTS; p++) {
                    int up = h * 4 + p;
                    float py = (ry + s_off[up * 2 + 1]) * (float)HSP - 0.5f;
                    float y0f = floorf(py);
                    float dy = py - y0f;
                    int y0 = (int)y0f;
                    float wy0 = ((unsigned)y0 < HSP) ? (1.f - dy) : 0.f;
                    float wy1 = ((unsigned)(y0 + 1) < HSP) ? dy : 0.f;
                    int cy0 = min(max(y0, 0), HSP - 1);
                    int cy1 = min(max(y0 + 1, 0), HSP - 1);
                    float waw = s_wx[up * 2 + xc] * s_aw[up];
                    int xcoord = s_cx[up * 2 + xc];
                    const uint4* r0 = (const uint4*)(basep + (cy0 * WSP + xcoord) * HD);
                    const uint4* r1 = (const uint4*)(basep + (cy1 * WSP + xcoord) * HD);
                    uint4 v0 = *r0;
                    uint4 v1 = *r1;
                    __half2 w0 = __float2half2_rn(waw * wy0);
                    __half2 w1 = __float2half2_rn(waw * wy1);
                    ac0 = __hfma2(*(__half2*)&v0.x, w0, ac0);
                    ac1 = __hfma2(*(__half2*)&v0.y, w0, ac1);
                    ac2 = __hfma2(*(__half2*)&v0.z, w0, ac2);
                    ac3 = __hfma2(*(__half2*)&v0.w, w0, ac3);
                    ac0 = __hfma2(*(__half2*)&v1.x, w1, ac0);
                    ac1 = __hfma2(*(__half2*)&v1.y, w1, ac1);
                    ac2 = __hfma2(*(__half2*)&v1.z, w1, ac2);
                    ac3 = __hfma2(*(__half2*)&v1.w, w1, ac3);
                    if (p == j) {
                        float wx0 = s_wx[up * 2 + 0];
                        float wx1 = s_wx[up * 2 + 1];
                        int cx0 = s_cx[up * 2 + 0];
                        int cx1 = s_cx[up * 2 + 1];
                        float g00 = Gh[cy0 * WSP + cx0];
                        float g01 = Gh[cy0 * WSP + cx1];
                        float g10 = Gh[cy1 * WSP + cx0];
                        float g11 = Gh[cy1 * WSP + cx1];
                        gdot = s_aw[up] * (wy0 * fmaf(wx0, g00, wx1 * g01)
                                         + wy1 * fmaf(wx0, g10, wx1 * g11));
                    }
                }
                // combine x-corner halves (lanes j and j^2)
                unsigned t;
                t = __shfl_xor_sync(0xffffffffu, *(unsigned*)&ac0, 2);
                ac0 = __hadd2(ac0, *(__half2*)&t);
                t = __shfl_xor_sync(0xffffffffu, *(unsigned*)&ac1, 2);
                ac1 = __hadd2(ac1, *(__half2*)&t);
                t = __shfl_xor_sync(0xffffffffu, *(unsigned*)&ac2, 2);
                ac2 = __hadd2(ac2, *(__half2*)&t);
                t = __shfl_xor_sync(0xffffffffu, *(unsigned*)&ac3, 2);
                ac3 = __hadd2(ac3, *(__half2*)&t);
                if (j < 2) {
                    float2 f0 = __half22float2(ac0);
                    float2 f1 = __half22float2(ac1);
                    float2 f2 = __half22float2(ac2);
                    float2 f3 = __half22float2(ac3);
                    int db = l * D + h * HD + co;
                    float4 w_;
                    w_.x = f0.x; w_.y = f0.y; w_.z = f1.x; w_.w = f1.y;
                    *(float4*)&s_msda[db] = w_;
                    float4 w2_;
                    w2_.x = f2.x; w2_.y = f2.y; w2_.z = f3.x; w2_.w = f3.y;
                    *(float4*)&s_msda[db + 4] = w2_;
                }
                // reduce fp32 logit partial over the 4 lanes (one point each)
                gdot += __shfl_xor_sync(0xffffffffu, gdot, 1);
                gdot += __shfl_xor_sync(0xffffffffu, gdot, 2);
                if (j == 0) s_lg[l * 9 + h] = gdot;
            }
        }
        __syncthreads();

        // ---- level softmax + argmax (warp 0; reduces 8 head-partials inline)
        if (tid < 32) {
            float v0 = -3.4e38f, v1 = -3.4e38f;
            if (tid < NL) {
                v0 = 0.f;
#pragma unroll
                for (int h = 0; h < NHEADS; h++) v0 += s_lg[tid * 9 + h];
            }
            if (tid + 32 < NL) {
                v1 = 0.f;
#pragma unroll
                for (int h = 0; h < NHEADS; h++) v1 += s_lg[(tid + 32) * 9 + h];
            }
            float bv; int bi;
            if (v1 > v0) { bv = v1; bi = tid + 32; }
            else         { bv = v0; bi = tid; }
#pragma unroll
            for (int o = 16; o; o >>= 1) {
                float ov = __shfl_down_sync(0xffffffffu, bv, o);
                int   oi = __shfl_down_sync(0xffffffffu, bi, o);
                if (ov > bv || (ov == bv && oi < bi)) { bv = ov; bi = oi; }
            }
            bv = __shfl_sync(0xffffffffu, bv, 0);
            float e0 = (tid < NL) ? expf(v0 - bv) : 0.f;
            float e1 = (tid + 32 < NL) ? expf(v1 - bv) : 0.f;
            float ssum = e0 + e1;
#pragma unroll
            for (int o = 16; o; o >>= 1)
                ssum += __shfl_xor_sync(0xffffffffu, ssum, o);
            float inv = 1.f / ssum;
            if (tid < NL) s_wts[tid] = e0 * inv;
            if (tid + 32 < NL) s_wts[tid + 32] = e1 * inv;
            if (tid == 0 && q < n_idx) out_idx[q] = (float)bi;
        }
        __syncthreads();

        // ---- weighted average over levels
        if (tid < D) {
            float acc = 0.f;
#pragma unroll 5
            for (int l = 0; l < NL; l++)
                acc = fmaf(s_wts[l], s_msda[l * D + tid], acc);
            s_avg[tid] = acc;
        }
        __syncthreads();

        // ---- final: out = avg @ W_out + b_out + 2*query  (k-split, 256 thr)
        {
            int ch = tid & 127, half_ = tid >> 7;
            int k0 = half_ * 64;
            float acc = 0.f;
#pragma unroll 8
            for (int k = 0; k < 64; k++)
                acc = fmaf(s_avg[k0 + k], W_out[(k0 + k) * D + ch], acc);
            if (half_) s_part[ch] = acc;
            __syncthreads();
            if (!half_)
                out[q * D + ch] = acc + s_part[ch] + b_out[ch] + 2.0f * s_q[ch];
        }
    }
}

// ---------------------------------------------------------------------------
extern "C" void kernel_launch(void* const* d_in, const int* in_sizes, int n_in,
                              void* d_out, int out_size) {
    const float* query  = (const float*)d_in[0];
    const float* value  = (const float*)d_in[1];
    const float* refp   = (const float*)d_in[2];
    const float* W_off  = (const float*)d_in[3];
    const float* b_off  = (const float*)d_in[4];
    const float* W_attn = (const float*)d_in[5];
    const float* b_attn = (const float*)d_in[6];
    const float* W_val  = (const float*)d_in[7];
    const float* b_val  = (const float*)d_in[8];
    const float* W_out  = (const float*)d_in[9];
    const float* b_out  = (const float*)d_in[10];
    const float* W_proj = (const float*)d_in[11];
    // b_proj (d_in[12]) unused: constant shift is softmax/argmax-invariant.

    float* out = (float*)d_out;

    int n_idx = out_size - NQ * D;
    if (n_idx < 0) n_idx = 0;
    if (n_idx > NQ) n_idx = NQ;

    int tail_n = out_size - (NQ * D + NQ);
    float* tailp = out + NQ * D + NQ;
    if (tail_n < 0) { tail_n = 0; tailp = out; }

    fused_kernel<<<GRID, TPB>>>(query, value, refp, W_off, b_off,
                                W_attn, b_attn, W_val, b_val,
                                W_out, b_out, W_proj,
                                out, out + NQ * D, n_idx, tailp, tail_n);
}